// round 14
// baseline (speedup 1.0000x reference)
#include <cuda_runtime.h>

#define NR   8192   // rows
#define CIN  512
#define CI   128
#define NB   4096   // value buckets
#define GRP  16     // buckets per group
#define NG   (NB / GRP)   // 256 groups
#define NSG  16           // supergroups (16 groups each)

// ---- scratch (device globals; no allocation allowed) ----
__device__ float d_u[CIN], d_v[CIN];
__device__ float d_cc[2];                 // ca, cb
__device__ float d_a[NR], d_b[NR];
__device__ float d_g[NR * CI];            // 4 MB
__device__ float d_bsv[NR];               // b values in bucketed order
__device__ int   d_si[NR];                // bucketed permutation
__device__ int   d_bstart[NB + 1];
__device__ unsigned d_bmin_ord, d_bmax_ord;
__device__ float d_brange[2];             // lo, scale
__device__ float2 d_T[NG * CI];           // per-group (sum g, sum b*g)
__device__ float2 d_C[NSG * CI];          // coarse supergroup totals (atomic)
__device__ float2 d_SB[(NB + 1) * CI];    // bucket-boundary suffix sums

// packed f32x2 FMA (Blackwell)
#define FMA_F32X2(d, a, b, c) \
    asm("fma.rn.f32x2 %0, %1, %2, %3;" : "=l"(d) : "l"(a), "l"(b), "l"(c))
#define PACK_F32X2(out, lo, hi) \
    asm("mov.b64 %0, {%1, %2};" : "=l"(out) : "f"(lo), "f"(hi))

__device__ __forceinline__ float f2lo(unsigned long long v) {
    return __uint_as_float((unsigned)(v & 0xFFFFFFFFull));
}
__device__ __forceinline__ float f2hi(unsigned long long v) {
    return __uint_as_float((unsigned)(v >> 32));
}
__device__ __forceinline__ unsigned ford(float f) {           // monotone float->uint
    unsigned b = __float_as_uint(f);
    return b ^ ((unsigned)(((int)b) >> 31) | 0x80000000u);
}
__device__ __forceinline__ float forddec(unsigned e) {
    return __uint_as_float((e & 0x80000000u) ? (e ^ 0x80000000u) : ~e);
}
__device__ __forceinline__ int bidx(float v, float lo, float scale) {
    int i = (int)((v - lo) * scale);                          // trunc: monotone
    return max(0, min(NB - 1, i));
}

// K1: u = Wt @ w1, v = Wp @ w2  (blocks 0-63 warp-per-t; block 64: cc + range init)
__global__ void __launch_bounds__(256) k_uv(const float* __restrict__ Wt,
                                            const float* __restrict__ bt,
                                            const float* __restrict__ Wp,
                                            const float* __restrict__ bp,
                                            const float* __restrict__ wcat) {
    __shared__ float sw[2 * CI];
    int tid = threadIdx.x;
    sw[tid] = wcat[tid];
    __syncthreads();
    if (blockIdx.x < 64) {
        int warp = tid >> 5, lane = tid & 31;
        int t = blockIdx.x * 8 + warp;
        float su = 0.f, sv = 0.f;
        #pragma unroll
        for (int m = 0; m < 4; m++) {
            int o = lane + 32 * m;
            su += Wt[t * CI + o] * sw[o];
            sv += Wp[t * CI + o] * sw[CI + o];
        }
        #pragma unroll
        for (int o = 16; o > 0; o >>= 1) {
            su += __shfl_xor_sync(0xFFFFFFFFu, su, o);
            sv += __shfl_xor_sync(0xFFFFFFFFu, sv, o);
        }
        if (lane == 0) { d_u[t] = su; d_v[t] = sv; }
    } else {
        __shared__ float redA[4], redB[4];
        int warp = tid >> 5, lane = tid & 31;
        float ra = 0.f, rb = 0.f;
        if (tid < CI) {
            ra = bt[tid] * sw[tid];
            rb = bp[tid] * sw[CI + tid];
        }
        #pragma unroll
        for (int o = 16; o > 0; o >>= 1) {
            ra += __shfl_xor_sync(0xFFFFFFFFu, ra, o);
            rb += __shfl_xor_sync(0xFFFFFFFFu, rb, o);
        }
        if (lane == 0 && warp < 4) { redA[warp] = ra; redB[warp] = rb; }
        __syncthreads();
        if (tid == 0) {
            d_cc[0] = redA[0] + redA[1] + redA[2] + redA[3];
            d_cc[1] = redB[0] + redB[1] + redB[2] + redB[3];
            d_bmin_ord = 0xFFFFFFFFu;      // re-init every launch (graph replay)
            d_bmax_ord = 0u;
        }
    }
}

// K2: a[i], b[i] + block min/max of b   (warp per row; 1024 blocks x 256)
__global__ void __launch_bounds__(256) k_ab(const float* __restrict__ x) {
    __shared__ float su[CIN], sv[CIN];
    __shared__ float sbv8[8];
    int tid = threadIdx.x;
    for (int i = tid; i < CIN; i += 256) { su[i] = d_u[i]; sv[i] = d_v[i]; }
    __syncthreads();
    int warp = tid >> 5, lane = tid & 31;
    int row = blockIdx.x * 8 + warp;
    const float4* xr4 = (const float4*)(x + row * CIN);
    const float4* su4 = (const float4*)su;
    const float4* sv4 = (const float4*)sv;
    float sa = 0.f, sb = 0.f;
    #pragma unroll
    for (int m = 0; m < 4; m++) {
        int j = lane + 32 * m;
        float4 xv = xr4[j];
        float4 uu = su4[j];
        float4 vv = sv4[j];
        sa += xv.x * uu.x + xv.y * uu.y + xv.z * uu.z + xv.w * uu.w;
        sb += xv.x * vv.x + xv.y * vv.y + xv.z * vv.z + xv.w * vv.w;
    }
    #pragma unroll
    for (int o = 16; o > 0; o >>= 1) {
        sa += __shfl_xor_sync(0xFFFFFFFFu, sa, o);
        sb += __shfl_xor_sync(0xFFFFFFFFu, sb, o);
    }
    if (lane == 0) {
        float bvv = sb + d_cc[1];
        d_a[row] = sa + d_cc[0];
        d_b[row] = bvv;
        sbv8[warp] = bvv;
    }
    __syncthreads();
    if (tid == 0) {
        float mn = sbv8[0], mx = sbv8[0];
        #pragma unroll
        for (int q = 1; q < 8; q++) { mn = fminf(mn, sbv8[q]); mx = fmaxf(mx, sbv8[q]); }
        atomicMin(&d_bmin_ord, ford(mn));
        atomicMax(&d_bmax_ord, ford(mx));
    }
}

// K3: g = x @ Wg + bg  (fp32x2 GEMM, split-N: 256 blocks = 128 row-tiles x 2
// col-halves; 64x64 tiles; 2 CTAs/SM). Register-prefetch + smem double-buffer.
__global__ void __launch_bounds__(256, 2) k_g(const float* __restrict__ x,
                                              const float* __restrict__ Wg,
                                              const float* __restrict__ bg) {
    __shared__ float xs[2][32][72];     // transposed x tile: xs[buf][k][row]
    __shared__ float ws[2][32][64];     // ws[buf][k][col-in-half]
    int tid = threadIdx.x;
    int tx = tid & 31, ty = tid >> 5;   // tx: 2 cols at tx*2; ty: 8 rows at ty*8
    int bm = (blockIdx.x >> 1) * 64;
    int bn = (blockIdx.x & 1) * 64;

    unsigned long long acc2[4][2];      // [rowpair][col]
    #pragma unroll
    for (int p = 0; p < 4; p++)
        #pragma unroll
        for (int c = 0; c < 2; c++) acc2[p][c] = 0ull;

    int lr  = tid & 63;          // x staging row (32 banks across warp)
    int lkq = (tid >> 6) * 8;    // k-offsets 0,8,16,24

    const float* xp0 = x + (bm + lr) * CIN + lkq;
    float4 xa = *(const float4*)xp0;
    float4 xb = *(const float4*)(xp0 + 4);
    float2 wr[4];
    #pragma unroll
    for (int s = 0; s < 4; s++)
        wr[s] = *(const float2*)(Wg + (ty + 8 * s) * CI + bn + tx * 2);

    #pragma unroll 1
    for (int k0 = 0; k0 < CIN; k0 += 32) {
        int buf = (k0 >> 5) & 1;
        xs[buf][lkq + 0][lr] = xa.x; xs[buf][lkq + 1][lr] = xa.y;
        xs[buf][lkq + 2][lr] = xa.z; xs[buf][lkq + 3][lr] = xa.w;
        xs[buf][lkq + 4][lr] = xb.x; xs[buf][lkq + 5][lr] = xb.y;
        xs[buf][lkq + 6][lr] = xb.z; xs[buf][lkq + 7][lr] = xb.w;
        #pragma unroll
        for (int s = 0; s < 4; s++)
            *(float2*)&ws[buf][ty + 8 * s][tx * 2] = wr[s];
        __syncthreads();
        if (k0 + 32 < CIN) {
            const float* xp = x + (bm + lr) * CIN + k0 + 32 + lkq;
            xa = *(const float4*)xp;
            xb = *(const float4*)(xp + 4);
            #pragma unroll
            for (int s = 0; s < 4; s++)
                wr[s] = *(const float2*)(Wg + (k0 + 32 + ty + 8 * s) * CI + bn + tx * 2);
        }
        #pragma unroll
        for (int kk = 0; kk < 32; kk++) {
            ulonglong2 xq0 = *(const ulonglong2*)&xs[buf][kk][ty * 8];     // rows 0-3 (2 pairs)
            ulonglong2 xq1 = *(const ulonglong2*)&xs[buf][kk][ty * 8 + 4]; // rows 4-7
            float2 wv = *(const float2*)&ws[buf][kk][tx * 2];
            unsigned long long w0, w1;
            PACK_F32X2(w0, wv.x, wv.x);
            PACK_F32X2(w1, wv.y, wv.y);
            FMA_F32X2(acc2[0][0], xq0.x, w0, acc2[0][0]);
            FMA_F32X2(acc2[0][1], xq0.x, w1, acc2[0][1]);
            FMA_F32X2(acc2[1][0], xq0.y, w0, acc2[1][0]);
            FMA_F32X2(acc2[1][1], xq0.y, w1, acc2[1][1]);
            FMA_F32X2(acc2[2][0], xq1.x, w0, acc2[2][0]);
            FMA_F32X2(acc2[2][1], xq1.x, w1, acc2[2][1]);
            FMA_F32X2(acc2[3][0], xq1.y, w0, acc2[3][0]);
            FMA_F32X2(acc2[3][1], xq1.y, w1, acc2[3][1]);
        }
        __syncthreads();
    }
    float2 bgv = *(const float2*)(bg + bn + tx * 2);
    #pragma unroll
    for (int p = 0; p < 4; p++) {
        int row0 = bm + ty * 8 + 2 * p;
        float2 o0, o1;
        o0.x = f2lo(acc2[p][0]) + bgv.x; o0.y = f2lo(acc2[p][1]) + bgv.y;
        o1.x = f2hi(acc2[p][0]) + bgv.x; o1.y = f2hi(acc2[p][1]) + bgv.y;
        *(float2*)&d_g[row0 * CI + bn + tx * 2] = o0;
        *(float2*)&d_g[(row0 + 1) * CI + bn + tx * 2] = o1;
    }
}

// K4: counting-sort b into NB value buckets (1 block, 1024 threads).
// Also zeroes the coarse totals d_C for this launch.
__global__ void __launch_bounds__(1024) k_bucket() {
    __shared__ int hist[NB];           // 16 KB
    __shared__ int scanbuf[1024];
    __shared__ float sls[2];           // lo, scale
    int tid = threadIdx.x;
    #pragma unroll
    for (int q = 0; q < NB / 1024; q++) hist[tid + 1024 * q] = 0;
    {   // zero coarse totals (4096 floats)
        float* cz = (float*)d_C;
        #pragma unroll
        for (int q = 0; q < (NSG * CI * 2) / 1024; q++) cz[tid + 1024 * q] = 0.f;
    }
    if (tid == 0) {
        float lo = forddec(d_bmin_ord);
        float hi = forddec(d_bmax_ord);
        float d = hi - lo;
        float scale = (d > 0.f) ? ((float)NB / d) : 0.f;
        sls[0] = lo; sls[1] = scale;
        d_brange[0] = lo; d_brange[1] = scale;
    }
    __syncthreads();
    float lo = sls[0], scale = sls[1];
    for (int j = tid; j < NR; j += 1024)
        atomicAdd(&hist[bidx(d_b[j], lo, scale)], 1);
    __syncthreads();
    int h0 = hist[4 * tid], h1 = hist[4 * tid + 1];
    int h2 = hist[4 * tid + 2], h3 = hist[4 * tid + 3];
    int tot = h0 + h1 + h2 + h3;
    scanbuf[tid] = tot;
    __syncthreads();
    #pragma unroll
    for (int off = 1; off < 1024; off <<= 1) {
        int v = (tid >= off) ? scanbuf[tid - off] : 0;
        __syncthreads();
        scanbuf[tid] += v;
        __syncthreads();
    }
    int excl = scanbuf[tid] - tot;
    d_bstart[4 * tid]     = excl;
    d_bstart[4 * tid + 1] = excl + h0;
    d_bstart[4 * tid + 2] = excl + h0 + h1;
    d_bstart[4 * tid + 3] = excl + h0 + h1 + h2;
    hist[4 * tid]     = excl;          // running counters for scatter
    hist[4 * tid + 1] = excl + h0;
    hist[4 * tid + 2] = excl + h0 + h1;
    hist[4 * tid + 3] = excl + h0 + h1 + h2;
    if (tid == 0) d_bstart[NB] = NR;
    __syncthreads();
    for (int j = tid; j < NR; j += 1024) {
        float bv = d_b[j];
        int pos = atomicAdd(&hist[bidx(bv, lo, scale)], 1);
        d_si[pos] = j;
        d_bsv[pos] = bv;
    }
}

// K5: per-group totals (float2) + atomic coarse supergroup totals  (NG blocks x 128)
__global__ void __launch_bounds__(CI) k_segsum() {
    __shared__ int ssi[CI];
    __shared__ float sbv[CI];
    int g = blockIdx.x, c = threadIdx.x;
    int pstart = d_bstart[g * GRP];
    int pend   = d_bstart[g * GRP + GRP];
    float t1 = 0.f, t2 = 0.f;
    for (int base = pstart; base < pend; base += CI) {
        int nchunk = min(CI, pend - base);
        if (c < nchunk) { ssi[c] = d_si[base + c]; sbv[c] = d_bsv[base + c]; }
        __syncthreads();
        for (int m = 0; m < nchunk; m++) {
            float gv = d_g[ssi[m] * CI + c];
            t1 += gv;
            t2 += sbv[m] * gv;
        }
        __syncthreads();
    }
    d_T[g * CI + c] = make_float2(t1, t2);
    int sg = g >> 4;
    atomicAdd(&d_C[sg * CI + c].x, t1);
    atomicAdd(&d_C[sg * CI + c].y, t2);
}

// K6: bucket-boundary suffix sums (NG blocks x 128).
// Suffix = coarse supergroups after mine + fine groups after me within mine.
__global__ void __launch_bounds__(CI) k_psum() {
    int g = blockIdx.x, c = threadIdx.x;
    int sg = g >> 4;
    float a1 = 0.f, a2 = 0.f;
    #pragma unroll 4
    for (int s = sg + 1; s < NSG; s++) {
        float2 cv = d_C[s * CI + c];
        a1 += cv.x; a2 += cv.y;
    }
    int gend = (sg + 1) * 16;
    #pragma unroll 4
    for (int gp = g + 1; gp < gend; gp++) {
        float2 tv = d_T[gp * CI + c];
        a1 += tv.x; a2 += tv.y;
    }
    for (int bk = GRP - 1; bk >= 0; bk--) {
        int gb = g * GRP + bk;
        d_SB[(gb + 1) * CI + c] = make_float2(a1, a2);
        int ps = d_bstart[gb], pe = d_bstart[gb + 1];
        for (int pos = ps; pos < pe; pos++) {
            int j = d_si[pos];
            float bv = d_bsv[pos];
            float gv = d_g[j * CI + c];
            a1 += gv;
            a2 += bv * gv;
        }
    }
}

// K7: z_i = (a_i*S1 + S2)/N; S = bucket suffix + exact boundary-bucket members
__global__ void __launch_bounds__(256) k_out(float* __restrict__ z) {
    int tid = threadIdx.x;
    int half = tid >> 7, c = tid & 127;
    int row = blockIdx.x * 2 + half;
    float av = d_a[row];
    float t = -av;
    float lo = d_brange[0], scale = d_brange[1];
    int bt = bidx(t, lo, scale);
    float2 sv = d_SB[(bt + 1) * CI + c];
    float s1 = sv.x, s2 = sv.y;
    int ps = d_bstart[bt], pe = d_bstart[bt + 1];
    for (int pos = ps; pos < pe; pos++) {
        float bv = d_bsv[pos];
        if (bv > t) {
            float gv = d_g[d_si[pos] * CI + c];
            s1 += gv;
            s2 += bv * gv;
        }
    }
    z[row * CI + c] = (av * s1 + s2) * (1.0f / (float)NR);
}

extern "C" void kernel_launch(void* const* d_in, const int* in_sizes, int n_in,
                              void* d_out, int out_size) {
    const float* x    = (const float*)d_in[0];
    const float* Wg   = (const float*)d_in[1];
    const float* bg   = (const float*)d_in[2];
    const float* Wt   = (const float*)d_in[3];
    const float* bt   = (const float*)d_in[4];
    const float* Wp   = (const float*)d_in[5];
    const float* bp   = (const float*)d_in[6];
    const float* wcat = (const float*)d_in[7];
    float* z = (float*)d_out;

    k_uv<<<65, 256>>>(Wt, bt, Wp, bp, wcat);
    k_ab<<<NR / 8, 256>>>(x);
    k_bucket<<<1, 1024>>>();
    k_g<<<(NR / 64) * 2, 256>>>(x, Wg, bg);
    k_segsum<<<NG, CI>>>();
    k_psum<<<NG, CI>>>();
    k_out<<<NR / 2, 256>>>(z);
}

// round 15
// speedup vs baseline: 1.1571x; 1.1571x over previous
#include <cuda_runtime.h>

#define NR   8192   // rows
#define CIN  512
#define CI   128
#define NB   4096   // value buckets
#define GRP  16     // buckets per group
#define NG   (NB / GRP)   // 256 groups
#define NSG  16           // supergroups (16 groups each)

// ---- scratch (device globals; no allocation allowed) ----
__device__ float d_u[CIN], d_v[CIN];
__device__ float d_cc[2];                 // ca, cb
__device__ float d_a[NR], d_b[NR];
__device__ float d_g[NR * CI];            // 4 MB
__device__ float d_bsv[NR];               // b values in bucketed order
__device__ int   d_si[NR];                // bucketed permutation
__device__ int   d_bstart[NB + 1];
__device__ unsigned d_bmin_ord, d_bmax_ord;
__device__ float d_brange[2];             // lo, scale
__device__ float2 d_T[NG * CI];           // per-group (sum g, sum b*g)
__device__ float2 d_C[NSG * CI];          // coarse supergroup totals (atomic)
__device__ float2 d_SB[(NB + 1) * CI];    // bucket-boundary suffix sums

// packed f32x2 FMA (Blackwell)
#define FMA_F32X2(d, a, b, c) \
    asm("fma.rn.f32x2 %0, %1, %2, %3;" : "=l"(d) : "l"(a), "l"(b), "l"(c))
#define PACK_F32X2(out, lo, hi) \
    asm("mov.b64 %0, {%1, %2};" : "=l"(out) : "f"(lo), "f"(hi))

__device__ __forceinline__ float f2lo(unsigned long long v) {
    return __uint_as_float((unsigned)(v & 0xFFFFFFFFull));
}
__device__ __forceinline__ float f2hi(unsigned long long v) {
    return __uint_as_float((unsigned)(v >> 32));
}
__device__ __forceinline__ unsigned ford(float f) {           // monotone float->uint
    unsigned b = __float_as_uint(f);
    return b ^ ((unsigned)(((int)b) >> 31) | 0x80000000u);
}
__device__ __forceinline__ float forddec(unsigned e) {
    return __uint_as_float((e & 0x80000000u) ? (e ^ 0x80000000u) : ~e);
}
__device__ __forceinline__ int bidx(float v, float lo, float scale) {
    int i = (int)((v - lo) * scale);                          // trunc: monotone
    return max(0, min(NB - 1, i));
}

// K1: u = Wt @ w1, v = Wp @ w2  (blocks 0-63 warp-per-t; block 64: cc + range init)
__global__ void __launch_bounds__(256) k_uv(const float* __restrict__ Wt,
                                            const float* __restrict__ bt,
                                            const float* __restrict__ Wp,
                                            const float* __restrict__ bp,
                                            const float* __restrict__ wcat) {
    __shared__ float sw[2 * CI];
    int tid = threadIdx.x;
    sw[tid] = wcat[tid];
    __syncthreads();
    if (blockIdx.x < 64) {
        int warp = tid >> 5, lane = tid & 31;
        int t = blockIdx.x * 8 + warp;
        float su = 0.f, sv = 0.f;
        #pragma unroll
        for (int m = 0; m < 4; m++) {
            int o = lane + 32 * m;
            su += Wt[t * CI + o] * sw[o];
            sv += Wp[t * CI + o] * sw[CI + o];
        }
        #pragma unroll
        for (int o = 16; o > 0; o >>= 1) {
            su += __shfl_xor_sync(0xFFFFFFFFu, su, o);
            sv += __shfl_xor_sync(0xFFFFFFFFu, sv, o);
        }
        if (lane == 0) { d_u[t] = su; d_v[t] = sv; }
    } else {
        __shared__ float redA[4], redB[4];
        int warp = tid >> 5, lane = tid & 31;
        float ra = 0.f, rb = 0.f;
        if (tid < CI) {
            ra = bt[tid] * sw[tid];
            rb = bp[tid] * sw[CI + tid];
        }
        #pragma unroll
        for (int o = 16; o > 0; o >>= 1) {
            ra += __shfl_xor_sync(0xFFFFFFFFu, ra, o);
            rb += __shfl_xor_sync(0xFFFFFFFFu, rb, o);
        }
        if (lane == 0 && warp < 4) { redA[warp] = ra; redB[warp] = rb; }
        __syncthreads();
        if (tid == 0) {
            d_cc[0] = redA[0] + redA[1] + redA[2] + redA[3];
            d_cc[1] = redB[0] + redB[1] + redB[2] + redB[3];
            d_bmin_ord = 0xFFFFFFFFu;      // re-init every launch (graph replay)
            d_bmax_ord = 0u;
        }
    }
}

// K2: a[i], b[i] + block min/max of b   (warp per row; 1024 blocks x 256)
__global__ void __launch_bounds__(256) k_ab(const float* __restrict__ x) {
    __shared__ float su[CIN], sv[CIN];
    __shared__ float sbv8[8];
    int tid = threadIdx.x;
    for (int i = tid; i < CIN; i += 256) { su[i] = d_u[i]; sv[i] = d_v[i]; }
    __syncthreads();
    int warp = tid >> 5, lane = tid & 31;
    int row = blockIdx.x * 8 + warp;
    const float4* xr4 = (const float4*)(x + row * CIN);
    const float4* su4 = (const float4*)su;
    const float4* sv4 = (const float4*)sv;
    float sa = 0.f, sb = 0.f;
    #pragma unroll
    for (int m = 0; m < 4; m++) {
        int j = lane + 32 * m;
        float4 xv = xr4[j];
        float4 uu = su4[j];
        float4 vv = sv4[j];
        sa += xv.x * uu.x + xv.y * uu.y + xv.z * uu.z + xv.w * uu.w;
        sb += xv.x * vv.x + xv.y * vv.y + xv.z * vv.z + xv.w * vv.w;
    }
    #pragma unroll
    for (int o = 16; o > 0; o >>= 1) {
        sa += __shfl_xor_sync(0xFFFFFFFFu, sa, o);
        sb += __shfl_xor_sync(0xFFFFFFFFu, sb, o);
    }
    if (lane == 0) {
        float bvv = sb + d_cc[1];
        d_a[row] = sa + d_cc[0];
        d_b[row] = bvv;
        sbv8[warp] = bvv;
    }
    __syncthreads();
    if (tid == 0) {
        float mn = sbv8[0], mx = sbv8[0];
        #pragma unroll
        for (int q = 1; q < 8; q++) { mn = fminf(mn, sbv8[q]); mx = fmaxf(mx, sbv8[q]); }
        atomicMin(&d_bmin_ord, ford(mn));
        atomicMax(&d_bmax_ord, ford(mx));
    }
}

// K3: g = x @ Wg + bg  (fp32x2 GEMM, 128 blocks x 256, 64x128 tiles)
// EXACT config that measured 31.6us (R7): reg-prefetch + smem double-buffer,
// conflict-free xs staging (lr = tid & 63).
__global__ void __launch_bounds__(256, 1) k_g(const float* __restrict__ x,
                                              const float* __restrict__ Wg,
                                              const float* __restrict__ bg) {
    __shared__ float xs[2][32][72];     // transposed x tile: xs[buf][k][row]
    __shared__ float ws[2][32][CI];
    int tid = threadIdx.x;
    int tx = tid & 31, ty = tid >> 5;
    int bm = blockIdx.x * 64;

    unsigned long long acc2[4][4];
    #pragma unroll
    for (int p = 0; p < 4; p++)
        #pragma unroll
        for (int c = 0; c < 4; c++) acc2[p][c] = 0ull;

    int lr  = tid & 63;          // within-warp lanes span 32 rows -> 32 banks
    int lkq = (tid >> 6) * 8;    // 0,8,16,24

    const float* xp0 = x + (bm + lr) * CIN + lkq;
    float4 xa = *(const float4*)xp0;
    float4 xb = *(const float4*)(xp0 + 4);
    float4 wr[4];
    #pragma unroll
    for (int s = 0; s < 4; s++)
        wr[s] = *(const float4*)(Wg + (ty + 8 * s) * CI + tx * 4);

    #pragma unroll 1
    for (int k0 = 0; k0 < CIN; k0 += 32) {
        int buf = (k0 >> 5) & 1;
        xs[buf][lkq + 0][lr] = xa.x; xs[buf][lkq + 1][lr] = xa.y;
        xs[buf][lkq + 2][lr] = xa.z; xs[buf][lkq + 3][lr] = xa.w;
        xs[buf][lkq + 4][lr] = xb.x; xs[buf][lkq + 5][lr] = xb.y;
        xs[buf][lkq + 6][lr] = xb.z; xs[buf][lkq + 7][lr] = xb.w;
        #pragma unroll
        for (int s = 0; s < 4; s++)
            *(float4*)&ws[buf][ty + 8 * s][tx * 4] = wr[s];
        __syncthreads();
        if (k0 + 32 < CIN) {
            const float* xp = x + (bm + lr) * CIN + k0 + 32 + lkq;
            xa = *(const float4*)xp;
            xb = *(const float4*)(xp + 4);
            #pragma unroll
            for (int s = 0; s < 4; s++)
                wr[s] = *(const float4*)(Wg + (k0 + 32 + ty + 8 * s) * CI + tx * 4);
        }
        #pragma unroll
        for (int kk = 0; kk < 32; kk++) {
            ulonglong2 xq0 = *(const ulonglong2*)&xs[buf][kk][ty * 8];
            ulonglong2 xq1 = *(const ulonglong2*)&xs[buf][kk][ty * 8 + 4];
            float4 wv = *(const float4*)&ws[buf][kk][tx * 4];
            unsigned long long w0, w1, w2, w3;
            PACK_F32X2(w0, wv.x, wv.x);
            PACK_F32X2(w1, wv.y, wv.y);
            PACK_F32X2(w2, wv.z, wv.z);
            PACK_F32X2(w3, wv.w, wv.w);
            FMA_F32X2(acc2[0][0], xq0.x, w0, acc2[0][0]);
            FMA_F32X2(acc2[0][1], xq0.x, w1, acc2[0][1]);
            FMA_F32X2(acc2[0][2], xq0.x, w2, acc2[0][2]);
            FMA_F32X2(acc2[0][3], xq0.x, w3, acc2[0][3]);
            FMA_F32X2(acc2[1][0], xq0.y, w0, acc2[1][0]);
            FMA_F32X2(acc2[1][1], xq0.y, w1, acc2[1][1]);
            FMA_F32X2(acc2[1][2], xq0.y, w2, acc2[1][2]);
            FMA_F32X2(acc2[1][3], xq0.y, w3, acc2[1][3]);
            FMA_F32X2(acc2[2][0], xq1.x, w0, acc2[2][0]);
            FMA_F32X2(acc2[2][1], xq1.x, w1, acc2[2][1]);
            FMA_F32X2(acc2[2][2], xq1.x, w2, acc2[2][2]);
            FMA_F32X2(acc2[2][3], xq1.x, w3, acc2[2][3]);
            FMA_F32X2(acc2[3][0], xq1.y, w0, acc2[3][0]);
            FMA_F32X2(acc2[3][1], xq1.y, w1, acc2[3][1]);
            FMA_F32X2(acc2[3][2], xq1.y, w2, acc2[3][2]);
            FMA_F32X2(acc2[3][3], xq1.y, w3, acc2[3][3]);
        }
        __syncthreads();
    }
    float4 bgv = *(const float4*)(bg + tx * 4);
    #pragma unroll
    for (int p = 0; p < 4; p++) {
        int row0 = bm + ty * 8 + 2 * p;
        float4 o0, o1;
        o0.x = f2lo(acc2[p][0]) + bgv.x; o0.y = f2lo(acc2[p][1]) + bgv.y;
        o0.z = f2lo(acc2[p][2]) + bgv.z; o0.w = f2lo(acc2[p][3]) + bgv.w;
        o1.x = f2hi(acc2[p][0]) + bgv.x; o1.y = f2hi(acc2[p][1]) + bgv.y;
        o1.z = f2hi(acc2[p][2]) + bgv.z; o1.w = f2hi(acc2[p][3]) + bgv.w;
        *(float4*)&d_g[row0 * CI + tx * 4] = o0;
        *(float4*)&d_g[(row0 + 1) * CI + tx * 4] = o1;
    }
}

// K4: counting-sort b into NB value buckets (1 block, 1024 threads).
// Also zeroes the coarse totals d_C for this launch.
__global__ void __launch_bounds__(1024) k_bucket() {
    __shared__ int hist[NB];           // 16 KB
    __shared__ int scanbuf[1024];
    __shared__ float sls[2];           // lo, scale
    int tid = threadIdx.x;
    #pragma unroll
    for (int q = 0; q < NB / 1024; q++) hist[tid + 1024 * q] = 0;
    {   // zero coarse totals (4096 floats)
        float* cz = (float*)d_C;
        #pragma unroll
        for (int q = 0; q < (NSG * CI * 2) / 1024; q++) cz[tid + 1024 * q] = 0.f;
    }
    if (tid == 0) {
        float lo = forddec(d_bmin_ord);
        float hi = forddec(d_bmax_ord);
        float d = hi - lo;
        float scale = (d > 0.f) ? ((float)NB / d) : 0.f;
        sls[0] = lo; sls[1] = scale;
        d_brange[0] = lo; d_brange[1] = scale;
    }
    __syncthreads();
    float lo = sls[0], scale = sls[1];
    for (int j = tid; j < NR; j += 1024)
        atomicAdd(&hist[bidx(d_b[j], lo, scale)], 1);
    __syncthreads();
    int h0 = hist[4 * tid], h1 = hist[4 * tid + 1];
    int h2 = hist[4 * tid + 2], h3 = hist[4 * tid + 3];
    int tot = h0 + h1 + h2 + h3;
    scanbuf[tid] = tot;
    __syncthreads();
    #pragma unroll
    for (int off = 1; off < 1024; off <<= 1) {
        int v = (tid >= off) ? scanbuf[tid - off] : 0;
        __syncthreads();
        scanbuf[tid] += v;
        __syncthreads();
    }
    int excl = scanbuf[tid] - tot;
    d_bstart[4 * tid]     = excl;
    d_bstart[4 * tid + 1] = excl + h0;
    d_bstart[4 * tid + 2] = excl + h0 + h1;
    d_bstart[4 * tid + 3] = excl + h0 + h1 + h2;
    hist[4 * tid]     = excl;          // running counters for scatter
    hist[4 * tid + 1] = excl + h0;
    hist[4 * tid + 2] = excl + h0 + h1;
    hist[4 * tid + 3] = excl + h0 + h1 + h2;
    if (tid == 0) d_bstart[NB] = NR;
    __syncthreads();
    for (int j = tid; j < NR; j += 1024) {
        float bv = d_b[j];
        int pos = atomicAdd(&hist[bidx(bv, lo, scale)], 1);
        d_si[pos] = j;
        d_bsv[pos] = bv;
    }
}

// K5: per-group totals (float2) + atomic coarse supergroup totals  (NG blocks x 128)
__global__ void __launch_bounds__(CI) k_segsum() {
    __shared__ int ssi[CI];
    __shared__ float sbv[CI];
    int g = blockIdx.x, c = threadIdx.x;
    int pstart = d_bstart[g * GRP];
    int pend   = d_bstart[g * GRP + GRP];
    float t1 = 0.f, t2 = 0.f;
    for (int base = pstart; base < pend; base += CI) {
        int nchunk = min(CI, pend - base);
        if (c < nchunk) { ssi[c] = d_si[base + c]; sbv[c] = d_bsv[base + c]; }
        __syncthreads();
        for (int m = 0; m < nchunk; m++) {
            float gv = d_g[ssi[m] * CI + c];
            t1 += gv;
            t2 += sbv[m] * gv;
        }
        __syncthreads();
    }
    d_T[g * CI + c] = make_float2(t1, t2);
    int sg = g >> 4;
    atomicAdd(&d_C[sg * CI + c].x, t1);
    atomicAdd(&d_C[sg * CI + c].y, t2);
}

// K6: bucket-boundary suffix sums (NG blocks x 128).
// Suffix = coarse supergroups after mine + fine groups after me within mine.
__global__ void __launch_bounds__(CI) k_psum() {
    int g = blockIdx.x, c = threadIdx.x;
    int sg = g >> 4;
    float a1 = 0.f, a2 = 0.f;
    #pragma unroll 4
    for (int s = sg + 1; s < NSG; s++) {
        float2 cv = d_C[s * CI + c];
        a1 += cv.x; a2 += cv.y;
    }
    int gend = (sg + 1) * 16;
    #pragma unroll 4
    for (int gp = g + 1; gp < gend; gp++) {
        float2 tv = d_T[gp * CI + c];
        a1 += tv.x; a2 += tv.y;
    }
    for (int bk = GRP - 1; bk >= 0; bk--) {
        int gb = g * GRP + bk;
        d_SB[(gb + 1) * CI + c] = make_float2(a1, a2);
        int ps = d_bstart[gb], pe = d_bstart[gb + 1];
        for (int pos = ps; pos < pe; pos++) {
            int j = d_si[pos];
            float bv = d_bsv[pos];
            float gv = d_g[j * CI + c];
            a1 += gv;
            a2 += bv * gv;
        }
    }
}

// K7: z_i = (a_i*S1 + S2)/N; S = bucket suffix + exact boundary-bucket members
__global__ void __launch_bounds__(256) k_out(float* __restrict__ z) {
    int tid = threadIdx.x;
    int half = tid >> 7, c = tid & 127;
    int row = blockIdx.x * 2 + half;
    float av = d_a[row];
    float t = -av;
    float lo = d_brange[0], scale = d_brange[1];
    int bt = bidx(t, lo, scale);
    float2 sv = d_SB[(bt + 1) * CI + c];
    float s1 = sv.x, s2 = sv.y;
    int ps = d_bstart[bt], pe = d_bstart[bt + 1];
    for (int pos = ps; pos < pe; pos++) {
        float bv = d_bsv[pos];
        if (bv > t) {
            float gv = d_g[d_si[pos] * CI + c];
            s1 += gv;
            s2 += bv * gv;
        }
    }
    z[row * CI + c] = (av * s1 + s2) * (1.0f / (float)NR);
}

extern "C" void kernel_launch(void* const* d_in, const int* in_sizes, int n_in,
                              void* d_out, int out_size) {
    const float* x    = (const float*)d_in[0];
    const float* Wg   = (const float*)d_in[1];
    const float* bg   = (const float*)d_in[2];
    const float* Wt   = (const float*)d_in[3];
    const float* bt   = (const float*)d_in[4];
    const float* Wp   = (const float*)d_in[5];
    const float* bp   = (const float*)d_in[6];
    const float* wcat = (const float*)d_in[7];
    float* z = (float*)d_out;

    k_uv<<<65, 256>>>(Wt, bt, Wp, bp, wcat);
    k_ab<<<NR / 8, 256>>>(x);
    k_bucket<<<1, 1024>>>();
    k_g<<<NR / 64, 256>>>(x, Wg, bg);
    k_segsum<<<NG, CI>>>();
    k_psum<<<NG, CI>>>();
    k_out<<<NR / 2, 256>>>(z);
}